// round 5
// baseline (speedup 1.0000x reference)
#include <cuda_runtime.h>

// GNN critic encoder, fully fused: one CTA per batch row.
// Tokens: 16 veh (DV=40) + 16 ped (DP=24) -> 32 tokens x E=128.
// Two GAT layers (H=4 heads, DH=32) + ELU, alive-masked mean pool -> 128.

#define HSTRIDE 1032   // per-head SMEM stride in words; 1032 % 32 == 8 -> heads land in distinct banks

__device__ __forceinline__ float elu1(float v) { return v > 0.f ? v : expm1f(v); }

template<int D>
__device__ __forceinline__ void embed_tokens(const float* __restrict__ obs_tok,
                                             const float* __restrict__ W,
                                             const float* __restrict__ bias,
                                             float* __restrict__ x2,
                                             int t0, int lane)
{
    float bb[4];
#pragma unroll
    for (int c = 0; c < 4; c++) bb[c] = __ldg(&bias[lane + 32 * c]);
    float acc[8][4];
#pragma unroll
    for (int r = 0; r < 8; r++)
#pragma unroll
        for (int c = 0; c < 4; c++) acc[r][c] = bb[c];
#pragma unroll 4
    for (int d = 0; d < D; d++) {
        float wv[4];
#pragma unroll
        for (int c = 0; c < 4; c++) wv[c] = __ldg(&W[d * 128 + lane + 32 * c]);
#pragma unroll
        for (int r = 0; r < 8; r++) {
            float xv = obs_tok[r * D + d];
#pragma unroll
            for (int c = 0; c < 4; c++) acc[r][c] += xv * wv[c];
        }
    }
#pragma unroll
    for (int r = 0; r < 8; r++)
#pragma unroll
        for (int c = 0; c < 4; c++)
            x2[c * HSTRIDE + (t0 + r) * 32 + lane] = acc[r][c];
}

__global__ __launch_bounds__(128, 4)
void gnn_critic_kernel(const float* __restrict__ gobs,
                       const float* __restrict__ Wv, const float* __restrict__ bv,
                       const float* __restrict__ Wp, const float* __restrict__ bp,
                       const float* __restrict__ w0g, const float* __restrict__ as0,
                       const float* __restrict__ ad0,
                       const float* __restrict__ w1g, const float* __restrict__ as1,
                       const float* __restrict__ ad1,
                       float* __restrict__ out)
{
    __shared__ float x2[4 * HSTRIDE];     // layer activations, head-strided layout
    __shared__ float h2[4 * HSTRIDE];     // per-layer h = x @ w, head-strided layout
    __shared__ float wstage[2048];        // 16x128 weight k-block; overlaid with obs row at start
    __shared__ float as_sh[32 * 4];
    __shared__ float ad_sh[32 * 4];
    __shared__ float alive[32];
    __shared__ float inv_cnt_sh;

    float* obs = wstage;                  // 1056 floats <= 2048; consumed before first GEMM staging

    const int tid  = threadIdx.x;
    const int lane = tid & 31;
    const int warp = tid >> 5;
    const int b    = blockIdx.x;

    // ---- load obs row ----
    const float* rowp = gobs + (long)b * 1056;
    for (int i = tid; i < 1056; i += 128) obs[i] = __ldg(&rowp[i]);
    __syncthreads();

    // ---- alive mask + all-dead fix + pool count ----
    if (warp == 0) {
        float v = (obs[1024 + lane] >= 0.5f) ? 1.0f : 0.0f;
        float s = v;
#pragma unroll
        for (int o = 16; o; o >>= 1) s += __shfl_xor_sync(0xffffffffu, s, o);
        float vv = (s < 0.5f) ? 1.0f : v;
        alive[lane] = vv;
        if (lane == 0) {
            float cnt = (s < 0.5f) ? 32.0f : s;
            inv_cnt_sh = 1.0f / fmaxf(cnt, 1.0f);
        }
    }
    __syncthreads();

    // ---- token embedding: warps 0-1 vehicles (D=40), warps 2-3 peds (D=24) ----
    if (warp < 2)
        embed_tokens<40>(obs + warp * 8 * 40, Wv, bv, x2, warp * 8, lane);
    else
        embed_tokens<24>(obs + 640 + (warp - 2) * 8 * 24, Wp, bp, x2, warp * 8, lane);
    __syncthreads();

    const int rg = warp;   // GEMM: this warp owns rows rg*8 .. rg*8+7
    const int cg = lane;   // and cols cg, cg+32, cg+64, cg+96

    for (int L = 0; L < 2; L++) {
        const float* w    = L ? w1g : w0g;
        const float* asrc = L ? as1 : as0;
        const float* adst = L ? ad1 : ad0;

        // ---- GEMM: h2 = x2 @ w  (32x128 @ 128x128), k staged 16 rows at a time ----
        float acc[8][4];
#pragma unroll
        for (int r = 0; r < 8; r++)
#pragma unroll
            for (int c = 0; c < 4; c++) acc[r][c] = 0.f;

        for (int kb = 0; kb < 8; kb++) {
            __syncthreads();   // previous wstage readers done (or obs consumed)
#pragma unroll
            for (int i = 0; i < 16; i++)
                wstage[i * 128 + tid] = __ldg(&w[kb * 2048 + i * 128 + tid]);
            __syncthreads();
#pragma unroll 4
            for (int kk = 0; kk < 16; kk++) {
                const int k = kb * 16 + kk;
                const float* xcol = &x2[(k >> 5) * HSTRIDE + (k & 31)];
                float wv[4];
#pragma unroll
                for (int c = 0; c < 4; c++) wv[c] = wstage[kk * 128 + cg + 32 * c];
#pragma unroll
                for (int r = 0; r < 8; r++) {
                    float xv = xcol[(rg * 8 + r) * 32];   // broadcast within warp
#pragma unroll
                    for (int c = 0; c < 4; c++) acc[r][c] += xv * wv[c];
                }
            }
        }
#pragma unroll
        for (int r = 0; r < 8; r++)
#pragma unroll
            for (int c = 0; c < 4; c++)
                h2[c * HSTRIDE + (rg * 8 + r) * 32 + cg] = acc[r][c];
        __syncthreads();

        // ---- alpha_src / alpha_dst : one (token, head) per thread ----
        {
            const int t = tid >> 2, hh = tid & 3;
            const float* hrow = &h2[hh * HSTRIDE + t * 32];
            float sa = 0.f, sd = 0.f;
#pragma unroll
            for (int d4 = 0; d4 < 8; d4++) {
                float4 hv = *(const float4*)&hrow[d4 * 4];
                float4 a1 = __ldg((const float4*)&asrc[hh * 32 + d4 * 4]);
                float4 a2 = __ldg((const float4*)&adst[hh * 32 + d4 * 4]);
                sa += hv.x * a1.x + hv.y * a1.y + hv.z * a1.z + hv.w * a1.w;
                sd += hv.x * a2.x + hv.y * a2.y + hv.z * a2.z + hv.w * a2.w;
            }
            as_sh[t * 4 + hh] = sa;
            ad_sh[t * 4 + hh] = sd;
        }
        __syncthreads();

        // ---- attention + aggregate + ELU : one (query i, head) per thread ----
        {
            const int i = tid >> 2, hh = tid & 3;
            const float a_i = as_sh[i * 4 + hh];
            float p[32];
            float m = -1e30f;
#pragma unroll
            for (int j = 0; j < 32; j++) {
                float e = a_i + ad_sh[j * 4 + hh];
                e = fmaxf(e, 0.2f * e);                  // leaky relu
                p[j] = (alive[j] > 0.5f) ? e : -1e30f;   // mask
                m = fmaxf(m, p[j]);
            }
            float s = 0.f;
#pragma unroll
            for (int j = 0; j < 32; j++) { p[j] = __expf(p[j] - m); s += p[j]; }
            const float inv = 1.0f / s;

            const float* hb = &h2[hh * HSTRIDE];
            float* xb = &x2[hh * HSTRIDE + i * 32];
#pragma unroll 1
            for (int d4 = 0; d4 < 8; d4++) {
                float4 a4 = make_float4(0.f, 0.f, 0.f, 0.f);
#pragma unroll
                for (int j = 0; j < 32; j++) {
                    float4 hv = *(const float4*)&hb[j * 32 + d4 * 4];
                    a4.x += p[j] * hv.x; a4.y += p[j] * hv.y;
                    a4.z += p[j] * hv.z; a4.w += p[j] * hv.w;
                }
                float4 o;
                o.x = elu1(a4.x * inv); o.y = elu1(a4.y * inv);
                o.z = elu1(a4.z * inv); o.w = elu1(a4.w * inv);
                *(float4*)&xb[d4 * 4] = o;
            }
        }
        __syncthreads();
    }

    // ---- masked mean pool: thread = output column ----
    {
        const int hh = tid >> 5, d = tid & 31;
        float s = 0.f;
#pragma unroll
        for (int i = 0; i < 32; i++)
            s += alive[i] * x2[hh * HSTRIDE + i * 32 + d];
        out[(long)b * 128 + tid] = s * inv_cnt_sh;
    }
}

extern "C" void kernel_launch(void* const* d_in, const int* in_sizes, int n_in,
                              void* d_out, int out_size)
{
    const float* gobs = (const float*)d_in[0];
    const float* Wv   = (const float*)d_in[1];
    const float* bv   = (const float*)d_in[2];
    const float* Wp   = (const float*)d_in[3];
    const float* bp   = (const float*)d_in[4];
    const float* w0   = (const float*)d_in[5];
    const float* as0  = (const float*)d_in[6];
    const float* ad0  = (const float*)d_in[7];
    const float* w1   = (const float*)d_in[8];
    const float* as1  = (const float*)d_in[9];
    const float* ad1  = (const float*)d_in[10];

    const int B = in_sizes[0] / 1056;

    gnn_critic_kernel<<<B, 128>>>(gobs, Wv, bv, Wp, bp,
                                  w0, as0, ad0, w1, as1, ad1,
                                  (float*)d_out);
}